// round 3
// baseline (speedup 1.0000x reference)
#include <cuda_runtime.h>
#include <cuda_bf16.h>
#include <math.h>

// Problem constants (fixed shapes)
#define NN    10000
#define EE    320000
#define ETOT  330000          // EE + NN self loops
#define DIN   256
#define HEADS 8
#define C1    64
#define F1    512             // HEADS*C1
#define DOUT  32
#define NEG   0.2f

// ---------------- scratch (no allocation allowed) ----------------
__device__ int      g_src[ETOT];
__device__ int      g_dst[ETOT];
__device__ int      g_mode64;
__device__ float    g_xl1[NN * F1];
__device__ float    g_xr1[NN * F1];
__device__ float    g_agg1[NN * F1];     // aggregate -> (in place) elu -> h1
__device__ float    g_alpha1[ETOT * HEADS];
__device__ unsigned g_amax1[NN * HEADS];
__device__ float    g_den1[NN * HEADS];
__device__ float    g_h2l[NN * DOUT];
__device__ float    g_h2r[NN * DOUT];
__device__ float    g_alpha2[ETOT];
__device__ unsigned g_amax2[NN];
__device__ float    g_den2[NN];

// monotonic float<->uint encoding for atomicMax on floats
__device__ __forceinline__ unsigned fenc(float f) {
    unsigned u = __float_as_uint(f);
    return (u & 0x80000000u) ? ~u : (u | 0x80000000u);
}
__device__ __forceinline__ float fdec(unsigned u) {
    return __uint_as_float((u & 0x80000000u) ? (u & 0x7FFFFFFFu) : ~u);
}
__device__ __forceinline__ float lrelu(float v) {
    return v > 0.f ? v : NEG * v;
}

// ---------------- edge index dtype probe + decode ----------------
// The reference asks for int64 but JAX (x64 disabled) silently yields int32.
// Probe reads only the first 64*8 bytes, in-bounds for either dtype.
__global__ void k_probe(const void* __restrict__ ei) {
    const long long* p64 = (const long long*)ei;
    int ok = 1;
    for (int i = 0; i < 64; i++) {
        long long v = p64[i];
        if (v < 0 || v >= NN) { ok = 0; break; }
    }
    g_mode64 = ok;
}

__global__ void k_decode(const void* __restrict__ ei) {
    int e = blockIdx.x * blockDim.x + threadIdx.x;
    if (e >= ETOT) return;
    if (e >= EE) { g_src[e] = g_dst[e] = e - EE; return; }
    if (g_mode64) {
        g_src[e] = (int)((const long long*)ei)[e];
        g_dst[e] = (int)((const long long*)ei)[EE + e];
    } else {
        g_src[e] = ((const int*)ei)[e];
        g_dst[e] = ((const int*)ei)[EE + e];
    }
}

// ---------------- init: zero everything ----------------
__global__ void k_init(float* out) {
    int i = blockIdx.x * blockDim.x + threadIdx.x;
    if (i < NN * F1) g_agg1[i] = 0.f;
    if (i < NN * HEADS) { g_amax1[i] = 0u; g_den1[i] = 0.f; }
    if (i < NN) { g_amax2[i] = 0u; g_den2[i] = 0.f; }
    if (i < NN * DOUT) out[i] = 0.f;
}

// ---------------- simple register-tiled fp32 GEMM ----------------
// C[M,Nc] = A[M,K] @ B[K,Nc];  K % 16 == 0, Nc % 4 == 0
#define BM 64
#define BN 64
#define BK 16
__global__ void k_gemm(const float* __restrict__ A, const float* __restrict__ B,
                       float* __restrict__ C, int M, int K, int Nc) {
    __shared__ float As[BK][BM];
    __shared__ float Bs[BK][BN];
    int tid = threadIdx.x;
    int bm = blockIdx.y * BM, bn = blockIdx.x * BN;
    int tx = tid & 15, ty = tid >> 4;

    int a_row = tid >> 2;          // 0..63
    int a_col = (tid & 3) * 4;     // 0,4,8,12
    int b_row = tid >> 4;          // 0..15
    int b_col = (tid & 15) * 4;    // 0..60

    float acc[4][4];
#pragma unroll
    for (int i = 0; i < 4; i++)
#pragma unroll
        for (int j = 0; j < 4; j++) acc[i][j] = 0.f;

    for (int k0 = 0; k0 < K; k0 += BK) {
        float4 av = make_float4(0.f, 0.f, 0.f, 0.f);
        int gr = bm + a_row;
        if (gr < M) av = *(const float4*)(A + (size_t)gr * K + k0 + a_col);
        As[a_col + 0][a_row] = av.x;
        As[a_col + 1][a_row] = av.y;
        As[a_col + 2][a_row] = av.z;
        As[a_col + 3][a_row] = av.w;

        float4 bv = make_float4(0.f, 0.f, 0.f, 0.f);
        int gc = bn + b_col;
        if (gc < Nc) bv = *(const float4*)(B + (size_t)(k0 + b_row) * Nc + gc);
        *(float4*)&Bs[b_row][b_col] = bv;

        __syncthreads();
#pragma unroll
        for (int k = 0; k < BK; k++) {
            float4 a4 = *(const float4*)&As[k][ty * 4];
            float4 b4 = *(const float4*)&Bs[k][tx * 4];
            float a[4] = {a4.x, a4.y, a4.z, a4.w};
            float b[4] = {b4.x, b4.y, b4.z, b4.w};
#pragma unroll
            for (int i = 0; i < 4; i++)
#pragma unroll
                for (int j = 0; j < 4; j++) acc[i][j] += a[i] * b[j];
        }
        __syncthreads();
    }
#pragma unroll
    for (int i = 0; i < 4; i++) {
        int row = bm + ty * 4 + i;
        if (row >= M) continue;
#pragma unroll
        for (int j = 0; j < 4; j++) {
            int col = bn + tx * 4 + j;
            if (col < Nc) C[(size_t)row * Nc + col] = acc[i][j];
        }
    }
}

// ---------------- layer 1 edge passes ----------------
// one thread per (edge, head): attention logit + segment max
__global__ void k_edge1_logits(const float* __restrict__ att1) {
    int t = blockIdx.x * blockDim.x + threadIdx.x;
    if (t >= ETOT * HEADS) return;
    int e = t >> 3, h = t & 7;
    int src = g_src[e], dst = g_dst[e];
    const float4* pl = (const float4*)(g_xl1 + (size_t)src * F1 + h * C1);
    const float4* pr = (const float4*)(g_xr1 + (size_t)dst * F1 + h * C1);
    const float4* pa = (const float4*)(att1 + h * C1);
    float s = 0.f;
#pragma unroll
    for (int i = 0; i < C1 / 4; i++) {
        float4 a = pl[i], b = pr[i], w = __ldg(&pa[i]);
        s += lrelu(a.x + b.x) * w.x;
        s += lrelu(a.y + b.y) * w.y;
        s += lrelu(a.z + b.z) * w.z;
        s += lrelu(a.w + b.w) * w.w;
    }
    g_alpha1[t] = s;
    atomicMax(&g_amax1[dst * HEADS + h], fenc(s));
}

__global__ void k_edge1_exp() {
    int t = blockIdx.x * blockDim.x + threadIdx.x;
    if (t >= ETOT * HEADS) return;
    int e = t >> 3, h = t & 7;
    int dst = g_dst[e];
    float m = fdec(g_amax1[dst * HEADS + h]);
    float ex = expf(g_alpha1[t] - m);
    g_alpha1[t] = ex;
    atomicAdd(&g_den1[dst * HEADS + h], ex);
}

// one thread per (edge, float4-chunk of 512): weighted scatter
__global__ void k_edge1_scatter() {
    long long tt = (long long)blockIdx.x * blockDim.x + threadIdx.x;
    if (tt >= (long long)ETOT * (F1 / 4)) return;
    int e = (int)(tt >> 7);       // F1/4 = 128 chunks
    int j = (int)(tt & 127);
    int h = j >> 4;               // (j*4)/64
    int src = g_src[e], dst = g_dst[e];
    float w = g_alpha1[e * HEADS + h] / (g_den1[dst * HEADS + h] + 1e-16f);
    float4 v = *(const float4*)(g_xl1 + (size_t)src * F1 + j * 4);
    float* o = g_agg1 + (size_t)dst * F1 + j * 4;
    atomicAdd(o + 0, v.x * w);
    atomicAdd(o + 1, v.y * w);
    atomicAdd(o + 2, v.z * w);
    atomicAdd(o + 3, v.w * w);
}

__global__ void k_bias_elu(const float* __restrict__ b1) {
    int i = blockIdx.x * blockDim.x + threadIdx.x;
    if (i >= NN * F1) return;
    float v = g_agg1[i] + b1[i & (F1 - 1)];
    g_agg1[i] = v > 0.f ? v : expm1f(v);
}

// ---------------- layer 2 edge passes (1 head, 32 ch) ----------------
__global__ void k_edge2_logits(const float* __restrict__ att2) {
    int e = blockIdx.x * blockDim.x + threadIdx.x;
    if (e >= ETOT) return;
    int src = g_src[e], dst = g_dst[e];
    const float4* pl = (const float4*)(g_h2l + (size_t)src * DOUT);
    const float4* pr = (const float4*)(g_h2r + (size_t)dst * DOUT);
    const float4* pa = (const float4*)att2;
    float s = 0.f;
#pragma unroll
    for (int i = 0; i < DOUT / 4; i++) {
        float4 a = pl[i], b = pr[i], w = __ldg(&pa[i]);
        s += lrelu(a.x + b.x) * w.x;
        s += lrelu(a.y + b.y) * w.y;
        s += lrelu(a.z + b.z) * w.z;
        s += lrelu(a.w + b.w) * w.w;
    }
    g_alpha2[e] = s;
    atomicMax(&g_amax2[dst], fenc(s));
}

__global__ void k_edge2_exp() {
    int e = blockIdx.x * blockDim.x + threadIdx.x;
    if (e >= ETOT) return;
    int dst = g_dst[e];
    float ex = expf(g_alpha2[e] - fdec(g_amax2[dst]));
    g_alpha2[e] = ex;
    atomicAdd(&g_den2[dst], ex);
}

__global__ void k_edge2_scatter(float* __restrict__ out) {
    int t = blockIdx.x * blockDim.x + threadIdx.x;
    if (t >= ETOT * (DOUT / 4)) return;
    int e = t >> 3, q = t & 7;
    int src = g_src[e], dst = g_dst[e];
    float w = g_alpha2[e] / (g_den2[dst] + 1e-16f);
    float4 v = *(const float4*)(g_h2l + (size_t)src * DOUT + q * 4);
    float* o = out + (size_t)dst * DOUT + q * 4;
    atomicAdd(o + 0, v.x * w);
    atomicAdd(o + 1, v.y * w);
    atomicAdd(o + 2, v.z * w);
    atomicAdd(o + 3, v.w * w);
}

// ---------------- final: +b2, log_softmax (warp per node) ----------------
__global__ void k_logsoftmax(float* __restrict__ out, const float* __restrict__ b2) {
    int warp = (blockIdx.x * blockDim.x + threadIdx.x) >> 5;
    int lane = threadIdx.x & 31;
    if (warp >= NN) return;
    float v = out[warp * DOUT + lane] + b2[lane];
    float m = v;
#pragma unroll
    for (int o = 16; o > 0; o >>= 1) m = fmaxf(m, __shfl_xor_sync(0xffffffffu, m, o));
    float s = expf(v - m);
#pragma unroll
    for (int o = 16; o > 0; o >>= 1) s += __shfl_xor_sync(0xffffffffu, s, o);
    out[warp * DOUT + lane] = v - m - logf(s);
}

// ---------------- launch ----------------
extern "C" void kernel_launch(void* const* d_in, const int* in_sizes, int n_in,
                              void* d_out, int out_size) {
    const float* x    = (const float*)d_in[0];
    const void*  ei   = d_in[1];
    const float* W1l  = (const float*)d_in[2];
    const float* W1r  = (const float*)d_in[3];
    const float* att1 = (const float*)d_in[4];
    const float* b1   = (const float*)d_in[5];
    const float* W2l  = (const float*)d_in[6];
    const float* W2r  = (const float*)d_in[7];
    const float* att2 = (const float*)d_in[8];
    const float* b2   = (const float*)d_in[9];
    float*       out  = (float*)d_out;

    const int TPB = 256;

    float *xl1, *xr1, *h1, *h2l, *h2r;
    cudaGetSymbolAddress((void**)&xl1, g_xl1);
    cudaGetSymbolAddress((void**)&xr1, g_xr1);
    cudaGetSymbolAddress((void**)&h1,  g_agg1);
    cudaGetSymbolAddress((void**)&h2l, g_h2l);
    cudaGetSymbolAddress((void**)&h2r, g_h2r);

    k_probe<<<1, 1>>>(ei);
    k_decode<<<(ETOT + TPB - 1) / TPB, TPB>>>(ei);
    k_init<<<(NN * F1 + TPB - 1) / TPB, TPB>>>(out);

    // layer 1 node transforms
    {
        dim3 grid(F1 / BN, (NN + BM - 1) / BM);
        k_gemm<<<grid, TPB>>>(x, W1l, xl1, NN, DIN, F1);
        k_gemm<<<grid, TPB>>>(x, W1r, xr1, NN, DIN, F1);
    }
    // layer 1 attention
    k_edge1_logits<<<(ETOT * HEADS + TPB - 1) / TPB, TPB>>>(att1);
    k_edge1_exp<<<(ETOT * HEADS + TPB - 1) / TPB, TPB>>>();
    {
        long long tot = (long long)ETOT * (F1 / 4);
        k_edge1_scatter<<<(unsigned)((tot + TPB - 1) / TPB), TPB>>>();
    }
    k_bias_elu<<<(NN * F1 + TPB - 1) / TPB, TPB>>>(b1);

    // layer 2 node transforms
    {
        dim3 grid((DOUT + BN - 1) / BN, (NN + BM - 1) / BM);
        k_gemm<<<grid, TPB>>>(h1, W2l, h2l, NN, F1, DOUT);
        k_gemm<<<grid, TPB>>>(h1, W2r, h2r, NN, F1, DOUT);
    }
    // layer 2 attention
    k_edge2_logits<<<(ETOT + TPB - 1) / TPB, TPB>>>(att2);
    k_edge2_exp<<<(ETOT + TPB - 1) / TPB, TPB>>>();
    k_edge2_scatter<<<(ETOT * (DOUT / 4) + TPB - 1) / TPB, TPB>>>(out);

    k_logsoftmax<<<(NN + 7) / 8, TPB>>>(out, b2);
}

// round 4
// speedup vs baseline: 2.2223x; 2.2223x over previous
#include <cuda_runtime.h>
#include <cuda_bf16.h>
#include <math.h>

#define NN    10000
#define EE    320000
#define ETOT  330000
#define DIN   256
#define HEADS 8
#define C1    64
#define F1    512
#define DOUT  32
#define NEG   0.2f

// ---------------- scratch ----------------
__device__ int      g_src[ETOT];
__device__ int      g_dst[ETOT];
__device__ int      g_mode64;
__device__ int      g_deg[NN];
__device__ int      g_off[NN + 1];
__device__ int      g_cur[NN];
__device__ int      g_csrc[ETOT];     // src id at sorted (by dst) position
__device__ int      g_ceid[ETOT];     // original edge id at sorted position
__device__ float    g_xl1[NN * F1];
__device__ float    g_xr1[NN * F1];
__device__ float    g_agg1[NN * F1];  // aggregated -> elu'd h1
__device__ float    g_alpha1[ETOT * HEADS];   // logits (edge order)
__device__ float    g_w1[ETOT * HEADS];       // normalized weights (sorted order)
__device__ float    g_h2l[NN * DOUT];
__device__ float    g_h2r[NN * DOUT];
__device__ float    g_alpha2[ETOT];
__device__ float    g_w2[ETOT];

__device__ __forceinline__ float lrelu(float v) { return v > 0.f ? v : NEG * v; }

// ---------------- edge dtype probe + decode ----------------
__global__ void k_probe(const void* __restrict__ ei) {
    const long long* p64 = (const long long*)ei;
    int ok = 1;
    for (int i = 0; i < 64; i++) {
        long long v = p64[i];
        if (v < 0 || v >= NN) { ok = 0; break; }
    }
    g_mode64 = ok;
}

__global__ void k_decode(const void* __restrict__ ei) {
    int e = blockIdx.x * blockDim.x + threadIdx.x;
    if (e >= ETOT) return;
    if (e >= EE) { g_src[e] = g_dst[e] = e - EE; return; }
    if (g_mode64) {
        g_src[e] = (int)((const long long*)ei)[e];
        g_dst[e] = (int)((const long long*)ei)[EE + e];
    } else {
        g_src[e] = ((const int*)ei)[e];
        g_dst[e] = ((const int*)ei)[EE + e];
    }
}

// ---------------- CSR build ----------------
__global__ void k_zero_deg() {
    int i = blockIdx.x * blockDim.x + threadIdx.x;
    if (i < NN) g_deg[i] = 0;
}

__global__ void k_count() {
    int e = blockIdx.x * blockDim.x + threadIdx.x;
    if (e >= ETOT) return;
    atomicAdd(&g_deg[g_dst[e]], 1);
}

// single-block exclusive scan over 10000 degrees
#define SCAN_T 1024
#define SCAN_PER ((NN + SCAN_T - 1) / SCAN_T)   // 10
__global__ void k_scan() {
    __shared__ int s[SCAN_T];
    int t = threadIdx.x;
    int base = t * SCAN_PER;
    int sum = 0;
#pragma unroll
    for (int i = 0; i < SCAN_PER; i++) {
        int idx = base + i;
        if (idx < NN) sum += g_deg[idx];
    }
    s[t] = sum;
    __syncthreads();
    // inclusive Hillis-Steele
    for (int o = 1; o < SCAN_T; o <<= 1) {
        int v = (t >= o) ? s[t - o] : 0;
        __syncthreads();
        s[t] += v;
        __syncthreads();
    }
    int run = s[t] - sum;   // exclusive chunk base
#pragma unroll
    for (int i = 0; i < SCAN_PER; i++) {
        int idx = base + i;
        if (idx < NN) {
            g_off[idx] = run;
            g_cur[idx] = run;
            run += g_deg[idx];
        }
    }
    if (t == SCAN_T - 1) g_off[NN] = ETOT;
}

__global__ void k_fill() {
    int e = blockIdx.x * blockDim.x + threadIdx.x;
    if (e >= ETOT) return;
    int pos = atomicAdd(&g_cur[g_dst[e]], 1);
    g_csrc[pos] = g_src[e];
    g_ceid[pos] = e;
}

// ---------------- GEMM: C[M,Nc] = A[M,K] @ B[K,Nc], 128x64 tile, 8x4/thread ----------------
#define BM 128
#define BN 64
#define BK 16
__global__ void k_gemm(const float* __restrict__ A, const float* __restrict__ B,
                       float* __restrict__ C, int M, int K, int Nc) {
    __shared__ float As[BK][BM];
    __shared__ float Bs[BK][BN];
    int tid = threadIdx.x;
    int bm = blockIdx.y * BM, bn = blockIdx.x * BN;
    int tx = tid & 15;        // 16 col groups * 4
    int ty = tid >> 4;        // 16 row groups * 8

    int a_row = tid >> 2;          // 0..63 (two loads: +0, +64)
    int a_col = (tid & 3) * 4;
    int b_row = tid >> 4;          // 0..15
    int b_col = (tid & 15) * 4;

    float acc[8][4];
#pragma unroll
    for (int i = 0; i < 8; i++)
#pragma unroll
        for (int j = 0; j < 4; j++) acc[i][j] = 0.f;

    for (int k0 = 0; k0 < K; k0 += BK) {
#pragma unroll
        for (int half = 0; half < 2; half++) {
            int r = a_row + half * 64;
            float4 av = make_float4(0.f, 0.f, 0.f, 0.f);
            int gr = bm + r;
            if (gr < M) av = *(const float4*)(A + (size_t)gr * K + k0 + a_col);
            As[a_col + 0][r] = av.x;
            As[a_col + 1][r] = av.y;
            As[a_col + 2][r] = av.z;
            As[a_col + 3][r] = av.w;
        }
        float4 bv = make_float4(0.f, 0.f, 0.f, 0.f);
        int gc = bn + b_col;
        if (gc < Nc) bv = *(const float4*)(B + (size_t)(k0 + b_row) * Nc + gc);
        *(float4*)&Bs[b_row][b_col] = bv;

        __syncthreads();
#pragma unroll
        for (int k = 0; k < BK; k++) {
            float4 a0 = *(const float4*)&As[k][ty * 8];
            float4 a1 = *(const float4*)&As[k][ty * 8 + 4];
            float4 b4 = *(const float4*)&Bs[k][tx * 4];
            float a[8] = {a0.x, a0.y, a0.z, a0.w, a1.x, a1.y, a1.z, a1.w};
            float b[4] = {b4.x, b4.y, b4.z, b4.w};
#pragma unroll
            for (int i = 0; i < 8; i++)
#pragma unroll
                for (int j = 0; j < 4; j++) acc[i][j] += a[i] * b[j];
        }
        __syncthreads();
    }
#pragma unroll
    for (int i = 0; i < 8; i++) {
        int row = bm + ty * 8 + i;
        if (row >= M) continue;
#pragma unroll
        for (int j = 0; j < 4; j++) {
            int col = bn + tx * 4 + j;
            if (col < Nc) C[(size_t)row * Nc + col] = acc[i][j];
        }
    }
}

// ---------------- layer 1 ----------------
// logits per (edge, head), edge order
__global__ void k_l1_logits(const float* __restrict__ att1) {
    int t = blockIdx.x * blockDim.x + threadIdx.x;
    if (t >= ETOT * HEADS) return;
    int e = t >> 3, h = t & 7;
    int src = g_src[e], dst = g_dst[e];
    const float4* pl = (const float4*)(g_xl1 + (size_t)src * F1 + h * C1);
    const float4* pr = (const float4*)(g_xr1 + (size_t)dst * F1 + h * C1);
    const float4* pa = (const float4*)(att1 + h * C1);
    float s = 0.f;
#pragma unroll
    for (int i = 0; i < C1 / 4; i++) {
        float4 a = pl[i], b = pr[i], w = __ldg(&pa[i]);
        s += lrelu(a.x + b.x) * w.x;
        s += lrelu(a.y + b.y) * w.y;
        s += lrelu(a.z + b.z) * w.z;
        s += lrelu(a.w + b.w) * w.w;
    }
    g_alpha1[t] = s;
}

// softmax per (node, head): write normalized weights at sorted positions
__global__ void k_l1_softmax() {
    int t = blockIdx.x * blockDim.x + threadIdx.x;
    if (t >= NN * HEADS) return;
    int node = t >> 3, h = t & 7;
    int beg = g_off[node], end = g_off[node + 1];
    float m = -1e30f;
    for (int p = beg; p < end; p++)
        m = fmaxf(m, g_alpha1[g_ceid[p] * HEADS + h]);
    float s = 0.f;
    for (int p = beg; p < end; p++) {
        float ex = expf(g_alpha1[g_ceid[p] * HEADS + h] - m);
        g_w1[p * HEADS + h] = ex;
        s += ex;
    }
    float inv = 1.f / (s + 1e-16f);
    for (int p = beg; p < end; p++)
        g_w1[p * HEADS + h] *= inv;
}

// gather-aggregate per node (block of 128 threads = 128 float4 = 512 ch), fused bias+elu
__global__ void k_l1_aggregate(const float* __restrict__ b1) {
    int node = blockIdx.x;
    int c4 = threadIdx.x;            // float4 index 0..127
    int h = c4 >> 4;                 // head of this chunk
    int beg = g_off[node], end = g_off[node + 1];
    float4 acc = make_float4(0.f, 0.f, 0.f, 0.f);
    for (int p = beg; p < end; p++) {
        int src = g_csrc[p];
        float w = g_w1[p * HEADS + h];
        float4 v = *(const float4*)(g_xl1 + (size_t)src * F1 + c4 * 4);
        acc.x += v.x * w; acc.y += v.y * w; acc.z += v.z * w; acc.w += v.w * w;
    }
    float4 bb = *(const float4*)(b1 + c4 * 4);
    acc.x += bb.x; acc.y += bb.y; acc.z += bb.z; acc.w += bb.w;
    acc.x = acc.x > 0.f ? acc.x : expm1f(acc.x);
    acc.y = acc.y > 0.f ? acc.y : expm1f(acc.y);
    acc.z = acc.z > 0.f ? acc.z : expm1f(acc.z);
    acc.w = acc.w > 0.f ? acc.w : expm1f(acc.w);
    *(float4*)(g_agg1 + (size_t)node * F1 + c4 * 4) = acc;
}

// ---------------- layer 2 ----------------
__global__ void k_l2_logits(const float* __restrict__ att2) {
    int e = blockIdx.x * blockDim.x + threadIdx.x;
    if (e >= ETOT) return;
    int src = g_src[e], dst = g_dst[e];
    const float4* pl = (const float4*)(g_h2l + (size_t)src * DOUT);
    const float4* pr = (const float4*)(g_h2r + (size_t)dst * DOUT);
    const float4* pa = (const float4*)att2;
    float s = 0.f;
#pragma unroll
    for (int i = 0; i < DOUT / 4; i++) {
        float4 a = pl[i], b = pr[i], w = __ldg(&pa[i]);
        s += lrelu(a.x + b.x) * w.x;
        s += lrelu(a.y + b.y) * w.y;
        s += lrelu(a.z + b.z) * w.z;
        s += lrelu(a.w + b.w) * w.w;
    }
    g_alpha2[e] = s;
}

__global__ void k_l2_softmax() {
    int node = blockIdx.x * blockDim.x + threadIdx.x;
    if (node >= NN) return;
    int beg = g_off[node], end = g_off[node + 1];
    float m = -1e30f;
    for (int p = beg; p < end; p++)
        m = fmaxf(m, g_alpha2[g_ceid[p]]);
    float s = 0.f;
    for (int p = beg; p < end; p++) {
        float ex = expf(g_alpha2[g_ceid[p]] - m);
        g_w2[p] = ex;
        s += ex;
    }
    float inv = 1.f / (s + 1e-16f);
    for (int p = beg; p < end; p++)
        g_w2[p] *= inv;
}

// warp per node: aggregate + b2 + log_softmax -> out
__global__ void k_l2_aggregate(float* __restrict__ out, const float* __restrict__ b2) {
    int node = (blockIdx.x * blockDim.x + threadIdx.x) >> 5;
    int lane = threadIdx.x & 31;
    if (node >= NN) return;
    int beg = g_off[node], end = g_off[node + 1];
    float acc = 0.f;
    for (int p = beg; p < end; p++) {
        int src = g_csrc[p];
        float w = g_w2[p];
        acc += g_h2l[(size_t)src * DOUT + lane] * w;
    }
    float v = acc + b2[lane];
    float m = v;
#pragma unroll
    for (int o = 16; o > 0; o >>= 1) m = fmaxf(m, __shfl_xor_sync(0xffffffffu, m, o));
    float s = expf(v - m);
#pragma unroll
    for (int o = 16; o > 0; o >>= 1) s += __shfl_xor_sync(0xffffffffu, s, o);
    out[node * DOUT + lane] = v - m - logf(s);
}

// ---------------- launch ----------------
extern "C" void kernel_launch(void* const* d_in, const int* in_sizes, int n_in,
                              void* d_out, int out_size) {
    const float* x    = (const float*)d_in[0];
    const void*  ei   = d_in[1];
    const float* W1l  = (const float*)d_in[2];
    const float* W1r  = (const float*)d_in[3];
    const float* att1 = (const float*)d_in[4];
    const float* b1   = (const float*)d_in[5];
    const float* W2l  = (const float*)d_in[6];
    const float* W2r  = (const float*)d_in[7];
    const float* att2 = (const float*)d_in[8];
    const float* b2   = (const float*)d_in[9];
    float*       out  = (float*)d_out;

    const int TPB = 256;

    float *xl1, *xr1, *h1, *h2l, *h2r;
    cudaGetSymbolAddress((void**)&xl1, g_xl1);
    cudaGetSymbolAddress((void**)&xr1, g_xr1);
    cudaGetSymbolAddress((void**)&h1,  g_agg1);
    cudaGetSymbolAddress((void**)&h2l, g_h2l);
    cudaGetSymbolAddress((void**)&h2r, g_h2r);

    // edge decode + CSR build
    k_probe<<<1, 1>>>(ei);
    k_decode<<<(ETOT + TPB - 1) / TPB, TPB>>>(ei);
    k_zero_deg<<<(NN + TPB - 1) / TPB, TPB>>>();
    k_count<<<(ETOT + TPB - 1) / TPB, TPB>>>();
    k_scan<<<1, SCAN_T>>>();
    k_fill<<<(ETOT + TPB - 1) / TPB, TPB>>>();

    // layer 1 node transforms
    {
        dim3 grid(F1 / BN, (NN + BM - 1) / BM);
        k_gemm<<<grid, TPB>>>(x, W1l, xl1, NN, DIN, F1);
        k_gemm<<<grid, TPB>>>(x, W1r, xr1, NN, DIN, F1);
    }
    // layer 1 attention
    k_l1_logits<<<(ETOT * HEADS + TPB - 1) / TPB, TPB>>>(att1);
    k_l1_softmax<<<(NN * HEADS + TPB - 1) / TPB, TPB>>>();
    k_l1_aggregate<<<NN, 128>>>(b1);

    // layer 2 node transforms
    {
        dim3 grid(1, (NN + BM - 1) / BM);
        k_gemm<<<grid, TPB>>>(h1, W2l, h2l, NN, F1, DOUT);
        k_gemm<<<grid, TPB>>>(h1, W2r, h2r, NN, F1, DOUT);
    }
    // layer 2 attention + output
    k_l2_logits<<<(ETOT + TPB - 1) / TPB, TPB>>>(att2);
    k_l2_softmax<<<(NN + TPB - 1) / TPB, TPB>>>();
    k_l2_aggregate<<<(NN * 32 + TPB - 1) / TPB, TPB>>>(out, b2);
}

// round 5
// speedup vs baseline: 5.5620x; 2.5028x over previous
#include <cuda_runtime.h>
#include <cuda_bf16.h>
#include <math.h>

#define NN    10000
#define EE    320000
#define ETOT  330000
#define DIN   256
#define HEADS 8
#define C1    64
#define F1    512
#define F1P   1024            // packed xl|xr row
#define DOUT  32
#define D2P   64              // packed h2l|h2r row
#define NEG   0.2f

// ---------------- scratch ----------------
__device__ int      g_src[ETOT];
__device__ int      g_dst[ETOT];
__device__ int      g_mode64;
__device__ int      g_deg[NN];
__device__ int      g_off[NN + 1];
__device__ int      g_cur[NN];
__device__ int      g_csrc[ETOT];        // src id sorted by dst
__device__ float    g_W1[DIN * F1P];     // [W1l | W1r] packed, 256x1024
__device__ float    g_W2[F1 * D2P];      // [W2l | W2r] packed, 512x64
__device__ float    g_xlr[NN * F1P];     // per node: [xl(512) | xr(512)]
__device__ float    g_agg1[NN * F1];     // elu'd h1
__device__ float    g_h2[NN * D2P];      // per node: [h2l(32) | h2r(32)]

__device__ __forceinline__ float lrelu(float v) { return v > 0.f ? v : NEG * v; }

// ---------------- edge dtype probe + decode ----------------
__global__ void k_probe(const void* __restrict__ ei) {
    const long long* p64 = (const long long*)ei;
    int ok = 1;
    for (int i = 0; i < 64; i++) {
        long long v = p64[i];
        if (v < 0 || v >= NN) { ok = 0; break; }
    }
    g_mode64 = ok;
}

__global__ void k_decode(const void* __restrict__ ei) {
    int e = blockIdx.x * blockDim.x + threadIdx.x;
    if (e >= ETOT) return;
    if (e >= EE) { g_src[e] = g_dst[e] = e - EE; return; }
    if (g_mode64) {
        g_src[e] = (int)((const long long*)ei)[e];
        g_dst[e] = (int)((const long long*)ei)[EE + e];
    } else {
        g_src[e] = ((const int*)ei)[e];
        g_dst[e] = ((const int*)ei)[EE + e];
    }
}

// ---------------- CSR build (dst-sorted) ----------------
__global__ void k_zero_deg() {
    int i = blockIdx.x * blockDim.x + threadIdx.x;
    if (i < NN) g_deg[i] = 0;
}
__global__ void k_count() {
    int e = blockIdx.x * blockDim.x + threadIdx.x;
    if (e >= ETOT) return;
    atomicAdd(&g_deg[g_dst[e]], 1);
}
#define SCAN_T 1024
#define SCAN_PER ((NN + SCAN_T - 1) / SCAN_T)
__global__ void k_scan() {
    __shared__ int s[SCAN_T];
    int t = threadIdx.x;
    int base = t * SCAN_PER;
    int sum = 0;
#pragma unroll
    for (int i = 0; i < SCAN_PER; i++) {
        int idx = base + i;
        if (idx < NN) sum += g_deg[idx];
    }
    s[t] = sum;
    __syncthreads();
    for (int o = 1; o < SCAN_T; o <<= 1) {
        int v = (t >= o) ? s[t - o] : 0;
        __syncthreads();
        s[t] += v;
        __syncthreads();
    }
    int run = s[t] - sum;
#pragma unroll
    for (int i = 0; i < SCAN_PER; i++) {
        int idx = base + i;
        if (idx < NN) {
            g_off[idx] = run;
            g_cur[idx] = run;
            run += g_deg[idx];
        }
    }
    if (t == SCAN_T - 1) g_off[NN] = ETOT;
}
__global__ void k_fill() {
    int e = blockIdx.x * blockDim.x + threadIdx.x;
    if (e >= ETOT) return;
    int pos = atomicAdd(&g_cur[g_dst[e]], 1);
    g_csrc[pos] = g_src[e];
}

// ---------------- weight packing ----------------
__global__ void k_pack1(const float* __restrict__ W1l, const float* __restrict__ W1r) {
    int i = blockIdx.x * blockDim.x + threadIdx.x;
    if (i >= DIN * F1P) return;
    int row = i >> 10, col = i & (F1P - 1);
    g_W1[i] = (col < F1) ? W1l[row * F1 + col] : W1r[row * F1 + col - F1];
}
__global__ void k_pack2(const float* __restrict__ W2l, const float* __restrict__ W2r) {
    int i = blockIdx.x * blockDim.x + threadIdx.x;
    if (i >= F1 * D2P) return;
    int row = i >> 6, col = i & (D2P - 1);
    g_W2[i] = (col < DOUT) ? W2l[row * DOUT + col] : W2r[row * DOUT + col - DOUT];
}

// ---------------- GEMM 128x64 tile ----------------
#define BM 128
#define BN 64
#define BK 16
__global__ void k_gemm(const float* __restrict__ A, const float* __restrict__ B,
                       float* __restrict__ C, int M, int K, int Nc) {
    __shared__ float As[BK][BM];
    __shared__ float Bs[BK][BN];
    int tid = threadIdx.x;
    int bm = blockIdx.y * BM, bn = blockIdx.x * BN;
    int tx = tid & 15, ty = tid >> 4;
    int a_row = tid >> 2, a_col = (tid & 3) * 4;
    int b_row = tid >> 4, b_col = (tid & 15) * 4;

    float acc[8][4];
#pragma unroll
    for (int i = 0; i < 8; i++)
#pragma unroll
        for (int j = 0; j < 4; j++) acc[i][j] = 0.f;

    for (int k0 = 0; k0 < K; k0 += BK) {
#pragma unroll
        for (int half = 0; half < 2; half++) {
            int r = a_row + half * 64;
            float4 av = make_float4(0.f, 0.f, 0.f, 0.f);
            int gr = bm + r;
            if (gr < M) av = *(const float4*)(A + (size_t)gr * K + k0 + a_col);
            As[a_col + 0][r] = av.x;
            As[a_col + 1][r] = av.y;
            As[a_col + 2][r] = av.z;
            As[a_col + 3][r] = av.w;
        }
        float4 bv = *(const float4*)(B + (size_t)(k0 + b_row) * Nc + bn + b_col);
        *(float4*)&Bs[b_row][b_col] = bv;

        __syncthreads();
#pragma unroll
        for (int k = 0; k < BK; k++) {
            float4 a0 = *(const float4*)&As[k][ty * 8];
            float4 a1 = *(const float4*)&As[k][ty * 8 + 4];
            float4 b4 = *(const float4*)&Bs[k][tx * 4];
            float a[8] = {a0.x, a0.y, a0.z, a0.w, a1.x, a1.y, a1.z, a1.w};
            float b[4] = {b4.x, b4.y, b4.z, b4.w};
#pragma unroll
            for (int i = 0; i < 8; i++)
#pragma unroll
                for (int j = 0; j < 4; j++) acc[i][j] += a[i] * b[j];
        }
        __syncthreads();
    }
#pragma unroll
    for (int i = 0; i < 8; i++) {
        int row = bm + ty * 8 + i;
        if (row >= M) continue;
#pragma unroll
        for (int j = 0; j < 4; j++)
            C[(size_t)row * Nc + bn + tx * 4 + j] = acc[i][j];
    }
}

// ---------------- GEMM 64x64 tile (skinny N) ----------------
__global__ void k_gemm64(const float* __restrict__ A, const float* __restrict__ B,
                         float* __restrict__ C, int M, int K, int Nc) {
    __shared__ float As[16][64];
    __shared__ float Bs[16][64];
    int tid = threadIdx.x;
    int bm = blockIdx.y * 64, bn = blockIdx.x * 64;
    int tx = tid & 15, ty = tid >> 4;
    int a_row = tid >> 2, a_col = (tid & 3) * 4;
    int b_row = tid >> 4, b_col = (tid & 15) * 4;

    float acc[4][4];
#pragma unroll
    for (int i = 0; i < 4; i++)
#pragma unroll
        for (int j = 0; j < 4; j++) acc[i][j] = 0.f;

    for (int k0 = 0; k0 < K; k0 += 16) {
        float4 av = make_float4(0.f, 0.f, 0.f, 0.f);
        int gr = bm + a_row;
        if (gr < M) av = *(const float4*)(A + (size_t)gr * K + k0 + a_col);
        As[a_col + 0][a_row] = av.x;
        As[a_col + 1][a_row] = av.y;
        As[a_col + 2][a_row] = av.z;
        As[a_col + 3][a_row] = av.w;
        float4 bv = *(const float4*)(B + (size_t)(k0 + b_row) * Nc + bn + b_col);
        *(float4*)&Bs[b_row][b_col] = bv;
        __syncthreads();
#pragma unroll
        for (int k = 0; k < 16; k++) {
            float4 a4 = *(const float4*)&As[k][ty * 4];
            float4 b4 = *(const float4*)&Bs[k][tx * 4];
            float a[4] = {a4.x, a4.y, a4.z, a4.w};
            float b[4] = {b4.x, b4.y, b4.z, b4.w};
#pragma unroll
            for (int i = 0; i < 4; i++)
#pragma unroll
                for (int j = 0; j < 4; j++) acc[i][j] += a[i] * b[j];
        }
        __syncthreads();
    }
#pragma unroll
    for (int i = 0; i < 4; i++) {
        int row = bm + ty * 4 + i;
        if (row >= M) continue;
#pragma unroll
        for (int j = 0; j < 4; j++)
            C[(size_t)row * Nc + bn + tx * 4 + j] = acc[i][j];
    }
}

// ---------------- fused layer-1 attention (flash-style online softmax) ----------------
// block = 128 threads = one node; thread owns float4 chunk c4 (head = c4>>4)
__global__ void k_l1_fused(const float* __restrict__ att1, const float* __restrict__ b1) {
    int node = blockIdx.x;
    int c4 = threadIdx.x;
    int beg = g_off[node], end = g_off[node + 1];

    float4 xr = *(const float4*)(g_xlr + (size_t)node * F1P + F1 + c4 * 4);
    float4 aw = __ldg(&((const float4*)att1)[c4]);

    float m = -1e30f, den = 0.f;
    float4 acc = make_float4(0.f, 0.f, 0.f, 0.f);

    for (int p = beg; p < end; p++) {
        int src = g_csrc[p];                     // uniform per warp -> broadcast
        float4 v = *(const float4*)(g_xlr + (size_t)src * F1P + c4 * 4);
        float part = lrelu(v.x + xr.x) * aw.x
                   + lrelu(v.y + xr.y) * aw.y
                   + lrelu(v.z + xr.z) * aw.z
                   + lrelu(v.w + xr.w) * aw.w;
#pragma unroll
        for (int o = 8; o; o >>= 1)
            part += __shfl_xor_sync(0xffffffffu, part, o);
        // online softmax update (per 16-lane head group, redundant per lane)
        if (part > m) {
            float sc = expf(m - part);
            den *= sc;
            acc.x *= sc; acc.y *= sc; acc.z *= sc; acc.w *= sc;
            m = part;
        }
        float w = expf(part - m);
        den += w;
        acc.x += w * v.x; acc.y += w * v.y; acc.z += w * v.z; acc.w += w * v.w;
    }
    float inv = 1.f / (den + 1e-16f);
    float4 bb = __ldg(&((const float4*)b1)[c4]);
    float r0 = acc.x * inv + bb.x;
    float r1 = acc.y * inv + bb.y;
    float r2 = acc.z * inv + bb.z;
    float r3 = acc.w * inv + bb.w;
    r0 = r0 > 0.f ? r0 : expm1f(r0);
    r1 = r1 > 0.f ? r1 : expm1f(r1);
    r2 = r2 > 0.f ? r2 : expm1f(r2);
    r3 = r3 > 0.f ? r3 : expm1f(r3);
    *(float4*)(g_agg1 + (size_t)node * F1 + c4 * 4) = make_float4(r0, r1, r2, r3);
}

// ---------------- fused layer-2 attention + bias + log_softmax ----------------
// warp per node; lane = output channel
__global__ void k_l2_fused(float* __restrict__ out, const float* __restrict__ att2,
                           const float* __restrict__ b2) {
    int node = (blockIdx.x * blockDim.x + threadIdx.x) >> 5;
    int lane = threadIdx.x & 31;
    if (node >= NN) return;
    int beg = g_off[node], end = g_off[node + 1];

    float xr = g_h2[(size_t)node * D2P + DOUT + lane];
    float aw = __ldg(att2 + lane);

    float m = -1e30f, den = 0.f, acc = 0.f;
    for (int p = beg; p < end; p++) {
        int src = g_csrc[p];
        float v = g_h2[(size_t)src * D2P + lane];
        float part = lrelu(v + xr) * aw;
#pragma unroll
        for (int o = 16; o; o >>= 1)
            part += __shfl_xor_sync(0xffffffffu, part, o);
        if (part > m) {
            float sc = expf(m - part);
            den *= sc; acc *= sc; m = part;
        }
        float w = expf(part - m);
        den += w;
        acc += w * v;
    }
    float v = acc / (den + 1e-16f) + __ldg(b2 + lane);
    float mx = v;
#pragma unroll
    for (int o = 16; o; o >>= 1) mx = fmaxf(mx, __shfl_xor_sync(0xffffffffu, mx, o));
    float s = expf(v - mx);
#pragma unroll
    for (int o = 16; o; o >>= 1) s += __shfl_xor_sync(0xffffffffu, s, o);
    out[node * DOUT + lane] = v - mx - logf(s);
}

// ---------------- launch ----------------
extern "C" void kernel_launch(void* const* d_in, const int* in_sizes, int n_in,
                              void* d_out, int out_size) {
    const float* x    = (const float*)d_in[0];
    const void*  ei   = d_in[1];
    const float* W1l  = (const float*)d_in[2];
    const float* W1r  = (const float*)d_in[3];
    const float* att1 = (const float*)d_in[4];
    const float* b1   = (const float*)d_in[5];
    const float* W2l  = (const float*)d_in[6];
    const float* W2r  = (const float*)d_in[7];
    const float* att2 = (const float*)d_in[8];
    const float* b2   = (const float*)d_in[9];
    float*       out  = (float*)d_out;

    const int TPB = 256;

    float *W1p, *W2p, *xlr, *h1, *h2;
    cudaGetSymbolAddress((void**)&W1p, g_W1);
    cudaGetSymbolAddress((void**)&W2p, g_W2);
    cudaGetSymbolAddress((void**)&xlr, g_xlr);
    cudaGetSymbolAddress((void**)&h1,  g_agg1);
    cudaGetSymbolAddress((void**)&h2,  g_h2);

    // edge decode + CSR
    k_probe<<<1, 1>>>(ei);
    k_decode<<<(ETOT + TPB - 1) / TPB, TPB>>>(ei);
    k_zero_deg<<<(NN + TPB - 1) / TPB, TPB>>>();
    k_count<<<(ETOT + TPB - 1) / TPB, TPB>>>();
    k_scan<<<1, SCAN_T>>>();
    k_fill<<<(ETOT + TPB - 1) / TPB, TPB>>>();

    // pack weights
    k_pack1<<<(DIN * F1P + TPB - 1) / TPB, TPB>>>(W1l, W1r);
    k_pack2<<<(F1 * D2P + TPB - 1) / TPB, TPB>>>(W2l, W2r);

    // layer 1: xlr = x @ [W1l|W1r]
    {
        dim3 grid(F1P / BN, (NN + BM - 1) / BM);
        k_gemm<<<grid, TPB>>>(x, W1p, xlr, NN, DIN, F1P);
    }
    // layer 1 fused attention -> h1
    k_l1_fused<<<NN, 128>>>(att1, b1);

    // layer 2: h2 = h1 @ [W2l|W2r]
    {
        dim3 grid(D2P / 64, (NN + 63) / 64);
        k_gemm64<<<grid, TPB>>>(h1, W2p, h2, NN, F1, D2P);
    }
    // layer 2 fused attention + output
    k_l2_fused<<<(NN * 32 + TPB - 1) / TPB, TPB>>>(out, att2, b2);
}

// round 7
// speedup vs baseline: 6.7496x; 1.2135x over previous
#include <cuda_runtime.h>
#include <cuda_bf16.h>
#include <math.h>

#define NN    10000
#define EE    320000
#define ETOT  330000
#define DIN   256
#define HEADS 8
#define C1    64
#define F1    512
#define F1P   1024            // packed xl|xr row
#define DOUT  32
#define D2P   64              // packed h2l|h2r row
#define NEG   0.2f

// ---------------- scratch ----------------
__device__ int      g_src[ETOT];
__device__ int      g_dst[ETOT];
__device__ int      g_mode64;
__device__ int      g_deg[NN];
__device__ int      g_off[NN + 1];
__device__ int      g_cur[NN];
__device__ int      g_csrc[ETOT];        // src id sorted by dst
__device__ float    g_W1[DIN * F1P];     // [W1l | W1r] packed, 256x1024
__device__ float    g_W2[F1 * D2P];      // [W2l | W2r] packed, 512x64
__device__ float    g_xlr[NN * F1P];     // per node: [xl(512) | xr(512)]
__device__ float    g_agg1[NN * F1];     // elu'd h1
__device__ float    g_h2[NN * D2P];      // per node: [h2l(32) | h2r(32)]

__device__ __forceinline__ float lrelu(float v) { return v > 0.f ? v : NEG * v; }

__device__ __forceinline__ float to_tf32(float x) {
    unsigned u;
    asm("cvt.rna.tf32.f32 %0, %1;" : "=r"(u) : "f"(x));
    return __uint_as_float(u);
}

// ---------------- edge dtype probe + decode ----------------
__global__ void k_probe(const void* __restrict__ ei) {
    const long long* p64 = (const long long*)ei;
    int ok = 1;
    for (int i = 0; i < 64; i++) {
        long long v = p64[i];
        if (v < 0 || v >= NN) { ok = 0; break; }
    }
    g_mode64 = ok;
}

__global__ void k_decode(const void* __restrict__ ei) {
    int e = blockIdx.x * blockDim.x + threadIdx.x;
    if (e >= ETOT) return;
    if (e >= EE) { g_src[e] = g_dst[e] = e - EE; return; }
    if (g_mode64) {
        g_src[e] = (int)((const long long*)ei)[e];
        g_dst[e] = (int)((const long long*)ei)[EE + e];
    } else {
        g_src[e] = ((const int*)ei)[e];
        g_dst[e] = ((const int*)ei)[EE + e];
    }
}

// ---------------- CSR build (dst-sorted) ----------------
__global__ void k_zero_deg() {
    int i = blockIdx.x * blockDim.x + threadIdx.x;
    if (i < NN) g_deg[i] = 0;
}
__global__ void k_count() {
    int e = blockIdx.x * blockDim.x + threadIdx.x;
    if (e >= ETOT) return;
    atomicAdd(&g_deg[g_dst[e]], 1);
}
#define SCAN_T 1024
#define SCAN_PER ((NN + SCAN_T - 1) / SCAN_T)
__global__ void k_scan() {
    __shared__ int s[SCAN_T];
    int t = threadIdx.x;
    int base = t * SCAN_PER;
    int sum = 0;
#pragma unroll
    for (int i = 0; i < SCAN_PER; i++) {
        int idx = base + i;
        if (idx < NN) sum += g_deg[idx];
    }
    s[t] = sum;
    __syncthreads();
    for (int o = 1; o < SCAN_T; o <<= 1) {
        int v = (t >= o) ? s[t - o] : 0;
        __syncthreads();
        s[t] += v;
        __syncthreads();
    }
    int run = s[t] - sum;
#pragma unroll
    for (int i = 0; i < SCAN_PER; i++) {
        int idx = base + i;
        if (idx < NN) {
            g_off[idx] = run;
            g_cur[idx] = run;
            run += g_deg[idx];
        }
    }
    if (t == SCAN_T - 1) g_off[NN] = ETOT;
}
__global__ void k_fill() {
    int e = blockIdx.x * blockDim.x + threadIdx.x;
    if (e >= ETOT) return;
    int pos = atomicAdd(&g_cur[g_dst[e]], 1);
    g_csrc[pos] = g_src[e];
}

// ---------------- weight packing ----------------
__global__ void k_pack1(const float* __restrict__ W1l, const float* __restrict__ W1r) {
    int i = blockIdx.x * blockDim.x + threadIdx.x;
    if (i >= DIN * F1P) return;
    int row = i >> 10, col = i & (F1P - 1);
    g_W1[i] = (col < F1) ? W1l[row * F1 + col] : W1r[row * F1 + col - F1];
}
__global__ void k_pack2(const float* __restrict__ W2l, const float* __restrict__ W2r) {
    int i = blockIdx.x * blockDim.x + threadIdx.x;
    if (i >= F1 * D2P) return;
    int row = i >> 6, col = i & (D2P - 1);
    g_W2[i] = (col < DOUT) ? W2l[row * DOUT + col] : W2r[row * DOUT + col - DOUT];
}

// ---------------- TF32 tensor-core GEMM ----------------
// C[M,Nc] = A[M,K] @ B[K,Nc]; tile 128x64x32; 128 threads = 4 warps (2x2),
// each warp 64x32 via m16n8k8 tf32 mma. Requires K % 32 == 0, Nc % 64 == 0.
#define TBM 128
#define TBN 64
#define TBK 32
__global__ void __launch_bounds__(128) k_gemm_tf32(
    const float* __restrict__ A, const float* __restrict__ B,
    float* __restrict__ C, int M, int K, int Nc) {
    __shared__ float As[TBK][TBM + 8];   // [k][m], pad 8 -> conflict-free frags
    __shared__ float Bs[TBK][TBN + 8];   // [k][n], pad 8

    int tid = threadIdx.x;
    int warp = tid >> 5, lane = tid & 31;
    int wm = (warp & 1) * 64;            // warp tile origin in block
    int wn = (warp >> 1) * 32;
    int bm = blockIdx.y * TBM, bn = blockIdx.x * TBN;
    int tr = lane >> 2, tc = lane & 3;

    float acc[4][4][4];
#pragma unroll
    for (int mt = 0; mt < 4; mt++)
#pragma unroll
        for (int nt = 0; nt < 4; nt++)
#pragma unroll
            for (int r = 0; r < 4; r++) acc[mt][nt][r] = 0.f;

    int arow = tid;                 // A: one row per thread, 8 float4 across k
    int brow = tid >> 2;            // B: row 0..31
    int bcol0 = (tid & 3) * 16;     // 4 float4 per thread

    for (int k0 = 0; k0 < K; k0 += TBK) {
        if (bm + arow < M) {
            const float* ap = A + (size_t)(bm + arow) * K + k0;
#pragma unroll
            for (int i = 0; i < 8; i++) {
                float4 v = *(const float4*)(ap + i * 4);
                As[i * 4 + 0][arow] = to_tf32(v.x);
                As[i * 4 + 1][arow] = to_tf32(v.y);
                As[i * 4 + 2][arow] = to_tf32(v.z);
                As[i * 4 + 3][arow] = to_tf32(v.w);
            }
        } else {
#pragma unroll
            for (int i = 0; i < 32; i++) As[i][arow] = 0.f;
        }
        {
            const float* bp = B + (size_t)(k0 + brow) * Nc + bn + bcol0;
#pragma unroll
            for (int i = 0; i < 4; i++) {
                float4 v = *(const float4*)(bp + i * 4);
                Bs[brow][bcol0 + i * 4 + 0] = to_tf32(v.x);
                Bs[brow][bcol0 + i * 4 + 1] = to_tf32(v.y);
                Bs[brow][bcol0 + i * 4 + 2] = to_tf32(v.z);
                Bs[brow][bcol0 + i * 4 + 3] = to_tf32(v.w);
            }
        }
        __syncthreads();

#pragma unroll
        for (int ks = 0; ks < TBK / 8; ks++) {
            int kb = ks * 8;
            unsigned af[4][4];
#pragma unroll
            for (int mt = 0; mt < 4; mt++) {
                int m0 = wm + mt * 16;
                af[mt][0] = __float_as_uint(As[kb + tc][m0 + tr]);
                af[mt][1] = __float_as_uint(As[kb + tc][m0 + tr + 8]);
                af[mt][2] = __float_as_uint(As[kb + tc + 4][m0 + tr]);
                af[mt][3] = __float_as_uint(As[kb + tc + 4][m0 + tr + 8]);
            }
            unsigned bf[4][2];
#pragma unroll
            for (int nt = 0; nt < 4; nt++) {
                int n0 = wn + nt * 8;
                bf[nt][0] = __float_as_uint(Bs[kb + tc][n0 + tr]);
                bf[nt][1] = __float_as_uint(Bs[kb + tc + 4][n0 + tr]);
            }
#pragma unroll
            for (int mt = 0; mt < 4; mt++)
#pragma unroll
                for (int nt = 0; nt < 4; nt++) {
                    asm volatile(
                        "mma.sync.aligned.m16n8k8.row.col.f32.tf32.tf32.f32 "
                        "{%0,%1,%2,%3}, {%4,%5,%6,%7}, {%8,%9}, {%0,%1,%2,%3};\n"
                        : "+f"(acc[mt][nt][0]), "+f"(acc[mt][nt][1]),
                          "+f"(acc[mt][nt][2]), "+f"(acc[mt][nt][3])
                        : "r"(af[mt][0]), "r"(af[mt][1]), "r"(af[mt][2]), "r"(af[mt][3]),
                          "r"(bf[nt][0]), "r"(bf[nt][1]));
                }
        }
        __syncthreads();
    }

#pragma unroll
    for (int mt = 0; mt < 4; mt++) {
        int row0 = bm + wm + mt * 16 + tr;
#pragma unroll
        for (int nt = 0; nt < 4; nt++) {
            int col0 = bn + wn + nt * 8 + 2 * tc;
            if (row0 < M)
                *(float2*)(C + (size_t)row0 * Nc + col0) =
                    make_float2(acc[mt][nt][0], acc[mt][nt][1]);
            if (row0 + 8 < M)
                *(float2*)(C + (size_t)(row0 + 8) * Nc + col0) =
                    make_float2(acc[mt][nt][2], acc[mt][nt][3]);
        }
    }
}

// ---------------- fused layer-1 attention (flash-style online softmax) ----------------
__global__ void k_l1_fused(const float* __restrict__ att1, const float* __restrict__ b1) {
    int node = blockIdx.x;
    int c4 = threadIdx.x;
    int beg = g_off[node], end = g_off[node + 1];

    float4 xr = *(const float4*)(g_xlr + (size_t)node * F1P + F1 + c4 * 4);
    float4 aw = __ldg(&((const float4*)att1)[c4]);

    float m = -1e30f, den = 0.f;
    float4 acc = make_float4(0.f, 0.f, 0.f, 0.f);

    for (int p = beg; p < end; p++) {
        int src = g_csrc[p];
        float4 v = *(const float4*)(g_xlr + (size_t)src * F1P + c4 * 4);
        float part = lrelu(v.x + xr.x) * aw.x
                   + lrelu(v.y + xr.y) * aw.y
                   + lrelu(v.z + xr.z) * aw.z
                   + lrelu(v.w + xr.w) * aw.w;
#pragma unroll
        for (int o = 8; o; o >>= 1)
            part += __shfl_xor_sync(0xffffffffu, part, o);
        if (part > m) {
            float sc = expf(m - part);
            den *= sc;
            acc.x *= sc; acc.y *= sc; acc.z *= sc; acc.w *= sc;
            m = part;
        }
        float w = expf(part - m);
        den += w;
        acc.x += w * v.x; acc.y += w * v.y; acc.z += w * v.z; acc.w += w * v.w;
    }
    float inv = 1.f / (den + 1e-16f);
    float4 bb = __ldg(&((const float4*)b1)[c4]);
    float r0 = acc.x * inv + bb.x;
    float r1 = acc.y * inv + bb.y;
    float r2 = acc.z * inv + bb.z;
    float r3 = acc.w * inv + bb.w;
    r0 = r0 > 0.f ? r0 : expm1f(r0);
    r1 = r1 > 0.f ? r1 : expm1f(r1);
    r2 = r2 > 0.f ? r2 : expm1f(r2);
    r3 = r3 > 0.f ? r3 : expm1f(r3);
    *(float4*)(g_agg1 + (size_t)node * F1 + c4 * 4) = make_float4(r0, r1, r2, r3);
}

// ---------------- fused layer-2 attention + bias + log_softmax ----------------
__global__ void k_l2_fused(float* __restrict__ out, const float* __restrict__ att2,
                           const float* __restrict__ b2) {
    int node = (blockIdx.x * blockDim.x + threadIdx.x) >> 5;
    int lane = threadIdx.x & 31;
    if (node >= NN) return;
    int beg = g_off[node], end = g_off[node + 1];

    float xr = g_h2[(size_t)node * D2P + DOUT + lane];
    float aw = __ldg(att2 + lane);

    float m = -1e30f, den = 0.f, acc = 0.f;
    for (int p = beg; p < end; p++) {
        int src = g_csrc[p];
        float v = g_h2[(size_t)src * D2P + lane];
        float part = lrelu(v + xr) * aw;
#pragma unroll
        for (int o = 16; o; o >>= 1)
            part += __shfl_xor_sync(0xffffffffu, part, o);
        if (part > m) {
            float sc = expf(m - part);
            den *= sc; acc *= sc; m = part;
        }
        float w = expf(part - m);
        den += w;
        acc += w * v;
    }
    float v = acc / (den + 1e-16f) + __ldg(b2 + lane);
    float mx = v;
#pragma unroll
    for (int o = 16; o; o >>= 1) mx = fmaxf(mx, __shfl_xor_sync(0xffffffffu, mx, o));
    float s = expf(v - mx);
#pragma unroll
    for (int o = 16; o; o >>= 1) s += __shfl_xor_sync(0xffffffffu, s, o);
    out[node * DOUT + lane] = v - mx - logf(s);
}

// ---------------- launch ----------------
extern "C" void kernel_launch(void* const* d_in, const int* in_sizes, int n_in,
                              void* d_out, int out_size) {
    const float* x    = (const float*)d_in[0];
    const void*  ei   = d_in[1];
    const float* W1l  = (const float*)d_in[2];
    const float* W1r  = (const float*)d_in[3];
    const float* att1 = (const float*)d_in[4];
    const float* b1   = (const float*)d_in[5];
    const float* W2l  = (const float*)d_in[6];
    const float* W2r  = (const float*)d_in[7];
    const float* att2 = (const float*)d_in[8];
    const float* b2   = (const float*)d_in[9];
    float*       out  = (float*)d_out;

    const int TPB = 256;

    float *W1p, *W2p, *xlr, *h1, *h2;
    cudaGetSymbolAddress((void**)&W1p, g_W1);
    cudaGetSymbolAddress((void**)&W2p, g_W2);
    cudaGetSymbolAddress((void**)&xlr, g_xlr);
    cudaGetSymbolAddress((void**)&h1,  g_agg1);
    cudaGetSymbolAddress((void**)&h2,  g_h2);

    // edge decode + CSR
    k_probe<<<1, 1>>>(ei);
    k_decode<<<(ETOT + TPB - 1) / TPB, TPB>>>(ei);
    k_zero_deg<<<(NN + TPB - 1) / TPB, TPB>>>();
    k_count<<<(ETOT + TPB - 1) / TPB, TPB>>>();
    k_scan<<<1, SCAN_T>>>();
    k_fill<<<(ETOT + TPB - 1) / TPB, TPB>>>();

    // pack weights
    k_pack1<<<(DIN * F1P + TPB - 1) / TPB, TPB>>>(W1l, W1r);
    k_pack2<<<(F1 * D2P + TPB - 1) / TPB, TPB>>>(W2l, W2r);

    // layer 1: xlr = x @ [W1l|W1r]   (tf32 tensor cores)
    {
        dim3 grid(F1P / TBN, (NN + TBM - 1) / TBM);
        k_gemm_tf32<<<grid, 128>>>(x, W1p, xlr, NN, DIN, F1P);
    }
    // layer 1 fused attention -> h1
    k_l1_fused<<<NN, 128>>>(att1, b1);

    // layer 2: h2 = h1 @ [W2l|W2r]   (tf32 tensor cores)
    {
        dim3 grid(D2P / TBN, (NN + TBM - 1) / TBM);
        k_gemm_tf32<<<grid, 128>>>(h1, W2p, h2, NN, F1, D2P);
    }
    // layer 2 fused attention + output
    k_l2_fused<<<(NN * 32 + TPB - 1) / TPB, TPB>>>(out, att2, b2);
}